// round 16
// baseline (speedup 1.0000x reference)
#include <cuda_runtime.h>
#include <cuda_fp16.h>
#include <math.h>
#include <stdint.h>

#define EMB 1024
#define HEADS 16
#define DH 64
#define BATCH 4
#define SEQ 2048
#define MROWS (BATCH * SEQ)   // 8192

// ---------------- scratch (device globals; no runtime allocation) ----------
__device__ __half g_x    [(size_t)MROWS * EMB];       // x fp16
__device__ __half g_wqkvB[(size_t)EMB * (3 * EMB)];   // [k][n] fp16
__device__ __half g_wfcB [(size_t)EMB * EMB];         // [k][n] fp16
__device__ __half g_qn   [(size_t)MROWS * EMB];       // q fp16, pre-scaled log2e/8
__device__ __half g_kn   [(size_t)MROWS * EMB];       // [m][h*64+d]
__device__ __half g_vn   [(size_t)MROWS * EMB];
__device__ __half g_ctx  [(size_t)MROWS * EMB];       // attention out fp16

#define QSCALE 0.18033688f    // 0.125 * log2(e)

// ---------------- helpers --------------------------------------------------
__device__ __forceinline__ uint32_t smem_u32(const void* p) {
    return (uint32_t)__cvta_generic_to_shared(p);
}
__device__ __forceinline__ void ldm_x4(uint32_t& r0, uint32_t& r1, uint32_t& r2, uint32_t& r3, uint32_t addr) {
    asm volatile("ldmatrix.sync.aligned.m8n8.x4.shared.b16 { %0, %1, %2, %3 }, [ %4 ];"
                 : "=r"(r0), "=r"(r1), "=r"(r2), "=r"(r3) : "r"(addr));
}
__device__ __forceinline__ void ldm_x4_t(uint32_t& r0, uint32_t& r1, uint32_t& r2, uint32_t& r3, uint32_t addr) {
    asm volatile("ldmatrix.sync.aligned.m8n8.x4.trans.shared.b16 { %0, %1, %2, %3 }, [ %4 ];"
                 : "=r"(r0), "=r"(r1), "=r"(r2), "=r"(r3) : "r"(addr));
}
__device__ __forceinline__ void mma16816(float* c, uint32_t a0, uint32_t a1, uint32_t a2, uint32_t a3,
                                         uint32_t b0, uint32_t b1) {
    asm volatile("mma.sync.aligned.m16n8k16.row.col.f32.f16.f16.f32 "
                 "{ %0, %1, %2, %3 }, { %4, %5, %6, %7 }, { %8, %9 }, { %0, %1, %2, %3 };"
                 : "+f"(c[0]), "+f"(c[1]), "+f"(c[2]), "+f"(c[3])
                 : "r"(a0), "r"(a1), "r"(a2), "r"(a3), "r"(b0), "r"(b1));
}
__device__ __forceinline__ uint32_t packh2(float a, float b) {
    __half2 h = __floats2half2_rn(a, b);
    return *(uint32_t*)&h;
}
__device__ __forceinline__ void cpa16(void* s, const void* g) {
    asm volatile("cp.async.cg.shared.global [ %0 ], [ %1 ], 16;"
                 :: "r"(smem_u32(s)), "l"(g));
}
__device__ __forceinline__ void cp_commit() {
    asm volatile("cp.async.commit_group;");
}
template <int N>
__device__ __forceinline__ void cp_wait() {
    asm volatile("cp.async.wait_group %0;" :: "n"(N));
}

// ---------------- data prep: fp32 -> fp16 ----------------------------------
template <int SEL>
__global__ void convert_kernel(const float* __restrict__ src) {
    __half* dst = (SEL == 0) ? g_wqkvB : (SEL == 1) ? g_wfcB : g_x;
    size_t i = ((size_t)blockIdx.x * blockDim.x + threadIdx.x) * 8;
    float4 f0 = *(const float4*)(src + i);
    float4 f1 = *(const float4*)(src + i + 4);
    __half2 h[4];
    h[0] = __floats2half2_rn(f0.x, f0.y);
    h[1] = __floats2half2_rn(f0.z, f0.w);
    h[2] = __floats2half2_rn(f1.x, f1.y);
    h[3] = __floats2half2_rn(f1.z, f1.w);
    *(uint4*)(dst + i) = *(uint4*)h;
}

// ---------------- HGEMM: R6 engine (32-K chunks), K=1024 -------------------
#define GSTG 3
#define SA_ST (128 * 40)
#define SB_ST (32 * 136)
#define HGEMM_SMEM ((GSTG * (SA_ST + SB_ST)) * 2)   // 56832 B

template <int EPI>
__global__ __launch_bounds__(128, 2) void hgemm_kernel(
    const float* __restrict__ bias, float* __restrict__ C, int N)
{
    extern __shared__ __half hsm[];
    __half* sAbase = hsm;
    __half* sBbase = hsm + GSTG * SA_ST;

    const __half* __restrict__ A = (EPI == 0) ? g_x : g_ctx;
    const __half* __restrict__ B = (EPI == 0) ? g_wqkvB : g_wfcB;

    const int tid = threadIdx.x;
    const int wid = tid >> 5, lane = tid & 31;
    const int wm = (wid & 1) * 64;
    const int wn = (wid >> 1) * 64;
    const int m0 = blockIdx.y * 128;
    const int n0 = blockIdx.x * 128;

    float acc[4][8][4];
#pragma unroll
    for (int mt = 0; mt < 4; mt++)
#pragma unroll
        for (int nt = 0; nt < 8; nt++)
#pragma unroll
            for (int r = 0; r < 4; r++) acc[mt][nt][r] = 0.f;

    const int ar0 = tid >> 2, ac0 = (tid & 3) * 8;
    const int br0 = tid >> 4, bc0 = (tid & 15) * 8;

#define LOAD_TILE(t, stg) do {                                                    \
        const int k0_ = (t) * 32;                                                \
        __half* sA_ = sAbase + (stg) * SA_ST;                                    \
        __half* sB_ = sBbase + (stg) * SB_ST;                                    \
        _Pragma("unroll")                                                         \
        for (int i_ = 0; i_ < 4; i_++) {                                         \
            const int r_ = ar0 + i_ * 32;                                        \
            cpa16(sA_ + r_ * 40 + ac0, A + (size_t)(m0 + r_) * EMB + k0_ + ac0); \
        }                                                                         \
        _Pragma("unroll")                                                         \
        for (int i_ = 0; i_ < 4; i_++) {                                         \
            const int r_ = br0 + i_ * 8;                                         \
            cpa16(sB_ + r_ * 136 + bc0,                                          \
                  B + (size_t)(k0_ + r_) * N + n0 + bc0);                        \
        }                                                                         \
        cp_commit();                                                             \
    } while (0)

    const int T = EMB / 32;    // 32
    LOAD_TILE(0, 0);
    LOAD_TILE(1, 1);

    int stg = 0;
    for (int t = 0; t < T; t++) {
        if (t < T - 1) cp_wait<1>(); else cp_wait<0>();
        __syncthreads();
        if (t + 2 < T) {
            int ns = stg + 2; if (ns >= GSTG) ns -= GSTG;
            LOAD_TILE(t + 2, ns);
        }
        __half* sA_ = sAbase + stg * SA_ST;
        __half* sB_ = sBbase + stg * SB_ST;
#pragma unroll
        for (int ks = 0; ks < 2; ks++) {
            uint32_t a[4][4];
#pragma unroll
            for (int mt = 0; mt < 4; mt++)
                ldm_x4(a[mt][0], a[mt][1], a[mt][2], a[mt][3],
                       smem_u32(sA_ + (wm + mt * 16 + (lane & 15)) * 40 + ks * 16 + (lane >> 4) * 8));
            uint32_t b[16];
#pragma unroll
            for (int nn = 0; nn < 4; nn++)
                ldm_x4_t(b[nn * 4 + 0], b[nn * 4 + 1], b[nn * 4 + 2], b[nn * 4 + 3],
                         smem_u32(sB_ + (ks * 16 + (lane & 15)) * 136 + wn + nn * 16 + (lane >> 4) * 8));
#pragma unroll
            for (int mt = 0; mt < 4; mt++)
#pragma unroll
                for (int nt = 0; nt < 8; nt++)
                    mma16816(acc[mt][nt], a[mt][0], a[mt][1], a[mt][2], a[mt][3],
                             b[nt * 2], b[nt * 2 + 1]);
        }
        stg++; if (stg >= GSTG) stg = 0;
    }
#undef LOAD_TILE

#pragma unroll
    for (int mt = 0; mt < 4; mt++) {
#pragma unroll
        for (int nt = 0; nt < 8; nt++) {
#pragma unroll
            for (int ri = 0; ri < 2; ri++) {
                const int m = m0 + wm + mt * 16 + (lane >> 2) + ri * 8;
                const int n = n0 + wn + nt * 8 + 2 * (lane & 3);
                float f0 = acc[mt][nt][ri * 2 + 0] + bias[n];
                float f1 = acc[mt][nt][ri * 2 + 1] + bias[n + 1];
                if (EPI == 1) {
                    float2 o;
                    o.x = f0;
                    o.y = f1;
                    *(float2*)(C + (size_t)m * N + n) = o;
                } else {
                    const int wh = n >> 10;     // 0=q 1=k 2=v
                    const int e  = n & 1023;
                    if (wh == 0) {
                        *(__half2*)(g_qn + (size_t)m * EMB + e) =
                            __floats2half2_rn(f0 * QSCALE, f1 * QSCALE);
                    } else if (wh == 1) {
                        *(__half2*)(g_kn + (size_t)m * EMB + e) = __floats2half2_rn(f0, f1);
                    } else {
                        *(__half2*)(g_vn + (size_t)m * EMB + e) = __floats2half2_rn(f0, f1);
                    }
                }
            }
        }
    }
}

// ---------------- flash attention: shared-KV dual q-tiles, exp2 ------------
// CTA handles q-tiles qtA = bx and qtB = 31-bx in ONE KV sweep (kv loaded once).
#define SQ_STRIDE 72
#define SK_STRIDE 72
#define SV_STRIDE 72
#define FLASH_SMEM ((128 * SQ_STRIDE + 2 * 64 * SK_STRIDE + 2 * 64 * SV_STRIDE) * 2)  // 55296 B

__global__ __launch_bounds__(128) void flash_kernel()
{
    extern __shared__ __half fsm[];
    __half* sQ  = fsm;                                  // 128 x 72: rows 0-63 = tile A, 64-127 = tile B
    __half* sK0 = fsm + 128 * SQ_STRIDE;
    __half* sV0 = sK0 + 2 * 64 * SK_STRIDE;

    const int tid = threadIdx.x, wid = tid >> 5, lane = tid & 31;
    const int hh = blockIdx.y, bz = blockIdx.z;

    const int qtA = blockIdx.x;                 // 0..15
    const int qtB = SEQ / 64 - 1 - blockIdx.x;  // 31..16
    const size_t mbase = (size_t)bz * SEQ;
    const __half* QgA = g_qn + (mbase + (size_t)qtA * 64) * EMB + hh * 64;
    const __half* QgB = g_qn + (mbase + (size_t)qtB * 64) * EMB + hh * 64;
    const __half* Kg = g_kn + mbase * EMB + hh * 64;
    const __half* Vg = g_vn + mbase * EMB + hh * 64;

    const int qrow0 = wid * 16 + (lane >> 2);   // row within a 64-row q tile

#define LOAD_KV(kt, stg) do {                                               \
        const __half* Kt_ = Kg + (size_t)(kt) * 64 * EMB;                  \
        const __half* Vt_ = Vg + (size_t)(kt) * 64 * EMB;                  \
        __half* sK_ = sK0 + (stg) * 64 * SK_STRIDE;                        \
        __half* sV_ = sV0 + (stg) * 64 * SV_STRIDE;                        \
        _Pragma("unroll")                                                   \
        for (int i_ = 0; i_ < 4; i_++) {                                   \
            int u_ = tid + i_ * 128;                                       \
            int r_ = u_ >> 3, c_ = (u_ & 7) * 8;                           \
            cpa16(sK_ + r_ * SK_STRIDE + c_, Kt_ + (size_t)r_ * EMB + c_); \
            cpa16(sV_ + r_ * SV_STRIDE + c_, Vt_ + (size_t)r_ * EMB + c_); \
        }                                                                   \
        cp_commit();                                                       \
    } while (0)

    // load both Q tiles (A rows 0-63, B rows 64-127)
#pragma unroll
    for (int i = 0; i < 4; i++) {
        int u = tid + i * 128;
        int row = u >> 3, c = (u & 7) * 8;
        *(uint4*)(sQ + row * SQ_STRIDE + c)          = *(const uint4*)(QgA + (size_t)row * EMB + c);
        *(uint4*)(sQ + (row + 64) * SQ_STRIDE + c)   = *(const uint4*)(QgB + (size_t)row * EMB + c);
    }
    LOAD_KV(0, 0);
    __syncthreads();

    uint32_t qfA[4][4], qfB[4][4];
#pragma unroll
    for (int ks = 0; ks < 4; ks++) {
        ldm_x4(qfA[ks][0], qfA[ks][1], qfA[ks][2], qfA[ks][3],
               smem_u32(sQ + (wid * 16 + (lane & 15)) * SQ_STRIDE + ks * 16 + (lane >> 4) * 8));
        ldm_x4(qfB[ks][0], qfB[ks][1], qfB[ks][2], qfB[ks][3],
               smem_u32(sQ + (64 + wid * 16 + (lane & 15)) * SQ_STRIDE + ks * 16 + (lane >> 4) * 8));
    }

    float OA[8][4], OB[8][4];
    float mA[2], lA[2], mB[2], lB[2];
#pragma unroll
    for (int dt = 0; dt < 8; dt++)
#pragma unroll
        for (int r = 0; r < 4; r++) { OA[dt][r] = 0.f; OB[dt][r] = 0.f; }
    mA[0] = mA[1] = mB[0] = mB[1] = -1e30f;
    lA[0] = lA[1] = lB[0] = lB[1] = 0.f;

    const int klr = (lane >> 4) * 8 + (lane & 7);
    const int klc = ((lane >> 3) & 1) * 8;
    const int vrow = lane & 15;
    const int vcol = (lane >> 4) * 8;

    // one tile-update: scores from QF against current sK_, softmax into O/m/l, PV.
#define TILE_COMPUTE(QF, O, MR, LR, QT) do {                                          \
        float S[8][4];                                                                \
        _Pragma("unroll")                                                             \
        for (int nt = 0; nt < 8; nt++)                                                \
            { S[nt][0] = 0.f; S[nt][1] = 0.f; S[nt][2] = 0.f; S[nt][3] = 0.f; }       \
        _Pragma("unroll")                                                             \
        for (int ks = 0; ks < 4; ks++) {                                              \
            _Pragma("unroll")                                                         \
            for (int jp = 0; jp < 4; jp++) {                                          \
                uint32_t b0, b1, b2, b3;                                              \
                ldm_x4(b0, b1, b2, b3,                                                \
                       smem_u32(sK_ + (jp * 16 + klr) * SK_STRIDE + ks * 16 + klc));  \
                mma16816(S[jp * 2 + 0], QF[ks][0], QF[ks][1], QF[ks][2], QF[ks][3], b0, b1); \
                mma16816(S[jp * 2 + 1], QF[ks][0], QF[ks][1], QF[ks][2], QF[ks][3], b2, b3); \
            }                                                                         \
        }                                                                             \
        if (kt == (QT)) {                                                             \
            _Pragma("unroll")                                                         \
            for (int nt = 0; nt < 8; nt++) {                                          \
                const int jc = nt * 8 + 2 * (lane & 3);                               \
                _Pragma("unroll")                                                     \
                for (int ri = 0; ri < 2; ri++) {                                      \
                    const int ii = qrow0 + ri * 8;                                    \
                    if (jc     > ii) S[nt][ri * 2 + 0] = -1e30f;                      \
                    if (jc + 1 > ii) S[nt][ri * 2 + 1] = -1e30f;                      \
                }                                                                     \
            }                                                                         \
        }                                                                             \
        _Pragma("unroll")                                                             \
        for (int ri = 0; ri < 2; ri++) {                                              \
            float tmax = -1e30f;                                                      \
            _Pragma("unroll")                                                         \
            for (int nt = 0; nt < 8; nt++)                                            \
                tmax = fmaxf(tmax, fmaxf(S[nt][ri * 2], S[nt][ri * 2 + 1]));          \
            tmax = fmaxf(tmax, __shfl_xor_sync(0xffffffffu, tmax, 1));                \
            tmax = fmaxf(tmax, __shfl_xor_sync(0xffffffffu, tmax, 2));                \
            const float mnew = fmaxf((MR)[ri], tmax);                                 \
            const float scale = exp2f((MR)[ri] - mnew);                               \
            float rs = 0.f;                                                           \
            _Pragma("unroll")                                                         \
            for (int nt = 0; nt < 8; nt++) {                                          \
                float p0 = exp2f(S[nt][ri * 2 + 0] - mnew);                           \
                float p1 = exp2f(S[nt][ri * 2 + 1] - mnew);                           \
                S[nt][ri * 2 + 0] = p0;                                               \
                S[nt][ri * 2 + 1] = p1;                                               \
                rs += p0 + p1;                                                        \
            }                                                                         \
            rs += __shfl_xor_sync(0xffffffffu, rs, 1);                                \
            rs += __shfl_xor_sync(0xffffffffu, rs, 2);                                \
            (LR)[ri] = (LR)[ri] * scale + rs;                                         \
            (MR)[ri] = mnew;                                                          \
            _Pragma("unroll")                                                         \
            for (int dt = 0; dt < 8; dt++) {                                          \
                (O)[dt][ri * 2 + 0] *= scale;                                         \
                (O)[dt][ri * 2 + 1] *= scale;                                         \
            }                                                                         \
        }                                                                             \
        _Pragma("unroll")                                                             \
        for (int kk = 0; kk < 4; kk++) {                                              \
            uint32_t a0 = packh2(S[kk * 2 + 0][0], S[kk * 2 + 0][1]);                 \
            uint32_t a1 = packh2(S[kk * 2 + 0][2], S[kk * 2 + 0][3]);                 \
            uint32_t a2 = packh2(S[kk * 2 + 1][0], S[kk * 2 + 1][1]);                 \
            uint32_t a3 = packh2(S[kk * 2 + 1][2], S[kk * 2 + 1][3]);                 \
            _Pragma("unroll")                                                         \
            for (int dp = 0; dp < 4; dp++) {                                          \
                uint32_t b0, b1, b2, b3;                                              \
                ldm_x4_t(b0, b1, b2, b3,                                              \
                         smem_u32(sV_ + (kk * 16 + vrow) * SV_STRIDE + dp * 16 + vcol)); \
                mma16816((O)[dp * 2 + 0], a0, a1, a2, a3, b0, b1);                    \
                mma16816((O)[dp * 2 + 1], a0, a1, a2, a3, b2, b3);                    \
            }                                                                         \
        }                                                                             \
    } while (0)

#pragma unroll 1
    for (int kt = 0; kt <= qtB; kt++) {
        cp_wait<0>();
        __syncthreads();
        if (kt < qtB) LOAD_KV(kt + 1, (kt + 1) & 1);

        const __half* sK_ = sK0 + (kt & 1) * 64 * SK_STRIDE;
        const __half* sV_ = sV0 + (kt & 1) * 64 * SV_STRIDE;

        if (kt <= qtA) {
            TILE_COMPUTE(qfA, OA, mA, lA, qtA);
        }
        TILE_COMPUTE(qfB, OB, mB, lB, qtB);
    }
#undef TILE_COMPUTE
#undef LOAD_KV

    // normalize + write both ctx tiles, fp16 [B*S, EMB]
#pragma unroll
    for (int ri = 0; ri < 2; ri++) {
        const float invA = 1.f / lA[ri];
        const float invB = 1.f / lB[ri];
        const size_t mgA = mbase + (size_t)qtA * 64 + qrow0 + ri * 8;
        const size_t mgB = mbase + (size_t)qtB * 64 + qrow0 + ri * 8;
#pragma unroll
        for (int dt = 0; dt < 8; dt++) {
            const int col = hh * 64 + dt * 8 + 2 * (lane & 3);
            *(__half2*)(g_ctx + mgA * EMB + col) =
                __floats2half2_rn(OA[dt][ri * 2 + 0] * invA, OA[dt][ri * 2 + 1] * invA);
            *(__half2*)(g_ctx + mgB * EMB + col) =
                __floats2half2_rn(OB[dt][ri * 2 + 0] * invB, OB[dt][ri * 2 + 1] * invB);
        }
    }
}

// ---------------------------------------------------------------------------
extern "C" void kernel_launch(void* const* d_in, const int* in_sizes, int n_in,
                              void* d_out, int out_size)
{
    const float* x     = (const float*)d_in[0];
    const float* w_qkv = (const float*)d_in[1];
    const float* b_qkv = (const float*)d_in[2];
    const float* w_fc  = (const float*)d_in[3];
    const float* b_fc  = (const float*)d_in[4];
    float* out = (float*)d_out;

    static int attr_done = 0;
    if (!attr_done) {
        cudaFuncSetAttribute(hgemm_kernel<0>, cudaFuncAttributeMaxDynamicSharedMemorySize, HGEMM_SMEM);
        cudaFuncSetAttribute(hgemm_kernel<1>, cudaFuncAttributeMaxDynamicSharedMemorySize, HGEMM_SMEM);
        cudaFuncSetAttribute(flash_kernel, cudaFuncAttributeMaxDynamicSharedMemorySize, FLASH_SMEM);
        attr_done = 1;
    }

    convert_kernel<2><<<MROWS * EMB / 8 / 256, 256>>>(x);
    convert_kernel<0><<<EMB * 3 * EMB / 8 / 256, 256>>>(w_qkv);
    convert_kernel<1><<<EMB * EMB / 8 / 256, 256>>>(w_fc);

    // 1) QKV projection
    hgemm_kernel<0><<<dim3(24, 64), 128, HGEMM_SMEM>>>(b_qkv, nullptr, 3 * EMB);

    // 2) causal flash attention (dual q-tiles share one KV sweep)
    flash_kernel<<<dim3(SEQ / 128, HEADS, BATCH), 128, FLASH_SMEM>>>();

    // 3) output projection
    hgemm_kernel<1><<<dim3(8, 64), 128, HGEMM_SMEM>>>(b_fc, out, EMB);
}

// round 17
// speedup vs baseline: 1.1623x; 1.1623x over previous
#include <cuda_runtime.h>
#include <cuda_fp16.h>
#include <math.h>
#include <stdint.h>

#define EMB 1024
#define HEADS 16
#define DH 64
#define BATCH 4
#define SEQ 2048
#define MROWS (BATCH * SEQ)   // 8192

// ---------------- scratch (device globals; no runtime allocation) ----------
__device__ __half g_x    [(size_t)MROWS * EMB];       // x fp16
__device__ __half g_wqkvB[(size_t)EMB * (3 * EMB)];   // [k][n] fp16
__device__ __half g_wfcB [(size_t)EMB * EMB];         // [k][n] fp16
__device__ __half g_qn   [(size_t)MROWS * EMB];       // q fp16, pre-scaled log2e/8
__device__ __half g_kn   [(size_t)MROWS * EMB];       // [m][h*64+d]
__device__ __half g_vn   [(size_t)MROWS * EMB];
__device__ __half g_ctx  [(size_t)MROWS * EMB];       // attention out fp16

#define QSCALE 0.18033688f    // 0.125 * log2(e)

// ---------------- helpers --------------------------------------------------
__device__ __forceinline__ uint32_t smem_u32(const void* p) {
    return (uint32_t)__cvta_generic_to_shared(p);
}
__device__ __forceinline__ void ldm_x4(uint32_t& r0, uint32_t& r1, uint32_t& r2, uint32_t& r3, uint32_t addr) {
    asm volatile("ldmatrix.sync.aligned.m8n8.x4.shared.b16 { %0, %1, %2, %3 }, [ %4 ];"
                 : "=r"(r0), "=r"(r1), "=r"(r2), "=r"(r3) : "r"(addr));
}
__device__ __forceinline__ void ldm_x4_t(uint32_t& r0, uint32_t& r1, uint32_t& r2, uint32_t& r3, uint32_t addr) {
    asm volatile("ldmatrix.sync.aligned.m8n8.x4.trans.shared.b16 { %0, %1, %2, %3 }, [ %4 ];"
                 : "=r"(r0), "=r"(r1), "=r"(r2), "=r"(r3) : "r"(addr));
}
__device__ __forceinline__ void mma16816(float* c, uint32_t a0, uint32_t a1, uint32_t a2, uint32_t a3,
                                         uint32_t b0, uint32_t b1) {
    asm volatile("mma.sync.aligned.m16n8k16.row.col.f32.f16.f16.f32 "
                 "{ %0, %1, %2, %3 }, { %4, %5, %6, %7 }, { %8, %9 }, { %0, %1, %2, %3 };"
                 : "+f"(c[0]), "+f"(c[1]), "+f"(c[2]), "+f"(c[3])
                 : "r"(a0), "r"(a1), "r"(a2), "r"(a3), "r"(b0), "r"(b1));
}
__device__ __forceinline__ uint32_t packh2(float a, float b) {
    __half2 h = __floats2half2_rn(a, b);
    return *(uint32_t*)&h;
}
__device__ __forceinline__ void cpa16(void* s, const void* g) {
    asm volatile("cp.async.cg.shared.global [ %0 ], [ %1 ], 16;"
                 :: "r"(smem_u32(s)), "l"(g));
}
__device__ __forceinline__ void cp_commit() {
    asm volatile("cp.async.commit_group;");
}
template <int N>
__device__ __forceinline__ void cp_wait() {
    asm volatile("cp.async.wait_group %0;" :: "n"(N));
}

// ---------------- data prep: single merged fp32 -> fp16 convert ------------
#define NX  ((size_t)MROWS * EMB)            // 8388608
#define NW0 ((size_t)EMB * 3 * EMB)          // 3145728
#define NW1 ((size_t)EMB * EMB)              // 1048576
__global__ void convert_all_kernel(const float* __restrict__ x,
                                   const float* __restrict__ wq,
                                   const float* __restrict__ wf) {
    size_t i = ((size_t)blockIdx.x * blockDim.x + threadIdx.x) * 8;
    const float* src;
    __half* dst;
    if (i < NX)              { src = x  + i;               dst = g_x     + i; }
    else if (i < NX + NW0)   { src = wq + (i - NX);        dst = g_wqkvB + (i - NX); }
    else                     { src = wf + (i - NX - NW0);  dst = g_wfcB  + (i - NX - NW0); }
    float4 f0 = *(const float4*)(src);
    float4 f1 = *(const float4*)(src + 4);
    __half2 h[4];
    h[0] = __floats2half2_rn(f0.x, f0.y);
    h[1] = __floats2half2_rn(f0.z, f0.w);
    h[2] = __floats2half2_rn(f1.x, f1.y);
    h[3] = __floats2half2_rn(f1.z, f1.w);
    *(uint4*)dst = *(uint4*)h;
}

// ---------------- HGEMM: 4-stage cp.async pipeline, K=1024 -----------------
#define GSTG 4
#define SA_ST (128 * 40)
#define SB_ST (32 * 136)
#define HGEMM_SMEM ((GSTG * (SA_ST + SB_ST)) * 2)   // 75776 B

template <int EPI>
__global__ __launch_bounds__(128, 2) void hgemm_kernel(
    const float* __restrict__ bias, float* __restrict__ C, int N)
{
    extern __shared__ __half hsm[];
    __half* sAbase = hsm;
    __half* sBbase = hsm + GSTG * SA_ST;

    const __half* __restrict__ A = (EPI == 0) ? g_x : g_ctx;
    const __half* __restrict__ B = (EPI == 0) ? g_wqkvB : g_wfcB;

    const int tid = threadIdx.x;
    const int wid = tid >> 5, lane = tid & 31;
    const int wm = (wid & 1) * 64;
    const int wn = (wid >> 1) * 64;
    const int m0 = blockIdx.y * 128;
    const int n0 = blockIdx.x * 128;

    float acc[4][8][4];
#pragma unroll
    for (int mt = 0; mt < 4; mt++)
#pragma unroll
        for (int nt = 0; nt < 8; nt++)
#pragma unroll
            for (int r = 0; r < 4; r++) acc[mt][nt][r] = 0.f;

    const int ar0 = tid >> 2, ac0 = (tid & 3) * 8;
    const int br0 = tid >> 4, bc0 = (tid & 15) * 8;

#define LOAD_TILE(t, stg) do {                                                    \
        const int k0_ = (t) * 32;                                                \
        __half* sA_ = sAbase + (stg) * SA_ST;                                    \
        __half* sB_ = sBbase + (stg) * SB_ST;                                    \
        _Pragma("unroll")                                                         \
        for (int i_ = 0; i_ < 4; i_++) {                                         \
            const int r_ = ar0 + i_ * 32;                                        \
            cpa16(sA_ + r_ * 40 + ac0, A + (size_t)(m0 + r_) * EMB + k0_ + ac0); \
        }                                                                         \
        _Pragma("unroll")                                                         \
        for (int i_ = 0; i_ < 4; i_++) {                                         \
            const int r_ = br0 + i_ * 8;                                         \
            cpa16(sB_ + r_ * 136 + bc0,                                          \
                  B + (size_t)(k0_ + r_) * N + n0 + bc0);                        \
        }                                                                         \
        cp_commit();                                                             \
    } while (0)

    const int T = EMB / 32;    // 32
    LOAD_TILE(0, 0);
    LOAD_TILE(1, 1);
    LOAD_TILE(2, 2);

    int stg = 0;
    for (int t = 0; t < T; t++) {
        if (t < T - 2)      cp_wait<2>();
        else if (t < T - 1) cp_wait<1>();
        else                cp_wait<0>();
        __syncthreads();
        if (t + 3 < T) {
            int ns = stg + 3; if (ns >= GSTG) ns -= GSTG;
            LOAD_TILE(t + 3, ns);
        }
        __half* sA_ = sAbase + stg * SA_ST;
        __half* sB_ = sBbase + stg * SB_ST;
#pragma unroll
        for (int ks = 0; ks < 2; ks++) {
            uint32_t a[4][4];
#pragma unroll
            for (int mt = 0; mt < 4; mt++)
                ldm_x4(a[mt][0], a[mt][1], a[mt][2], a[mt][3],
                       smem_u32(sA_ + (wm + mt * 16 + (lane & 15)) * 40 + ks * 16 + (lane >> 4) * 8));
            uint32_t b[16];
#pragma unroll
            for (int nn = 0; nn < 4; nn++)
                ldm_x4_t(b[nn * 4 + 0], b[nn * 4 + 1], b[nn * 4 + 2], b[nn * 4 + 3],
                         smem_u32(sB_ + (ks * 16 + (lane & 15)) * 136 + wn + nn * 16 + (lane >> 4) * 8));
#pragma unroll
            for (int mt = 0; mt < 4; mt++)
#pragma unroll
                for (int nt = 0; nt < 8; nt++)
                    mma16816(acc[mt][nt], a[mt][0], a[mt][1], a[mt][2], a[mt][3],
                             b[nt * 2], b[nt * 2 + 1]);
        }
        stg++; if (stg >= GSTG) stg = 0;
    }
#undef LOAD_TILE

#pragma unroll
    for (int mt = 0; mt < 4; mt++) {
#pragma unroll
        for (int nt = 0; nt < 8; nt++) {
#pragma unroll
            for (int ri = 0; ri < 2; ri++) {
                const int m = m0 + wm + mt * 16 + (lane >> 2) + ri * 8;
                const int n = n0 + wn + nt * 8 + 2 * (lane & 3);
                float f0 = acc[mt][nt][ri * 2 + 0] + bias[n];
                float f1 = acc[mt][nt][ri * 2 + 1] + bias[n + 1];
                if (EPI == 1) {
                    float2 o;
                    o.x = f0;
                    o.y = f1;
                    *(float2*)(C + (size_t)m * N + n) = o;
                } else {
                    const int wh = n >> 10;     // 0=q 1=k 2=v
                    const int e  = n & 1023;
                    if (wh == 0) {
                        *(__half2*)(g_qn + (size_t)m * EMB + e) =
                            __floats2half2_rn(f0 * QSCALE, f1 * QSCALE);
                    } else if (wh == 1) {
                        *(__half2*)(g_kn + (size_t)m * EMB + e) = __floats2half2_rn(f0, f1);
                    } else {
                        *(__half2*)(g_vn + (size_t)m * EMB + e) = __floats2half2_rn(f0, f1);
                    }
                }
            }
        }
    }
}

// ---------------- flash attention: R14 engine (paired q-tiles, exp2) -------
#define SQ_STRIDE 72
#define SK_STRIDE 72
#define SV_STRIDE 72
#define FLASH_SMEM ((64 * SQ_STRIDE + 2 * 64 * SK_STRIDE + 2 * 64 * SV_STRIDE) * 2)  // 46080 B

__global__ __launch_bounds__(128) void flash_kernel()
{
    extern __shared__ __half fsm[];
    __half* sQ  = fsm;
    __half* sK0 = fsm + 64 * SQ_STRIDE;
    __half* sV0 = sK0 + 2 * 64 * SK_STRIDE;

    const int tid = threadIdx.x, wid = tid >> 5, lane = tid & 31;
    const int hh = blockIdx.y, bz = blockIdx.z;

    const size_t mbase = (size_t)bz * SEQ;
    const __half* Kg = g_kn + mbase * EMB + hh * 64;
    const __half* Vg = g_vn + mbase * EMB + hh * 64;

    const int qrow0 = wid * 16 + (lane >> 2);

#define LOAD_KV(kt, stg) do {                                               \
        const __half* Kt_ = Kg + (size_t)(kt) * 64 * EMB;                  \
        const __half* Vt_ = Vg + (size_t)(kt) * 64 * EMB;                  \
        __half* sK_ = sK0 + (stg) * 64 * SK_STRIDE;                        \
        __half* sV_ = sV0 + (stg) * 64 * SV_STRIDE;                        \
        _Pragma("unroll")                                                   \
        for (int i_ = 0; i_ < 4; i_++) {                                   \
            int u_ = tid + i_ * 128;                                       \
            int r_ = u_ >> 3, c_ = (u_ & 7) * 8;                           \
            cpa16(sK_ + r_ * SK_STRIDE + c_, Kt_ + (size_t)r_ * EMB + c_); \
            cpa16(sV_ + r_ * SV_STRIDE + c_, Vt_ + (size_t)r_ * EMB + c_); \
        }                                                                   \
        cp_commit();                                                       \
    } while (0)

    // Two complementary q-tiles per CTA: qt = bx and 31 - bx  (work = 33 tiles)
#pragma unroll 1
    for (int pass = 0; pass < 2; pass++) {
        const int qt = (pass == 0) ? blockIdx.x : (SEQ / 64 - 1 - blockIdx.x);
        const __half* Qg = g_qn + (mbase + (size_t)qt * 64) * EMB + hh * 64;

        __syncthreads();   // previous pass fully done with sQ / sK / sV
#pragma unroll
        for (int i = 0; i < 4; i++) {
            int u = tid + i * 128;
            int row = u >> 3, c = (u & 7) * 8;
            *(uint4*)(sQ + row * SQ_STRIDE + c) = *(const uint4*)(Qg + (size_t)row * EMB + c);
        }
        LOAD_KV(0, 0);
        __syncthreads();

        uint32_t qf[4][4];
#pragma unroll
        for (int ks = 0; ks < 4; ks++)
            ldm_x4(qf[ks][0], qf[ks][1], qf[ks][2], qf[ks][3],
                   smem_u32(sQ + (wid * 16 + (lane & 15)) * SQ_STRIDE + ks * 16 + (lane >> 4) * 8));

        float O[8][4];
#pragma unroll
        for (int dt = 0; dt < 8; dt++)
#pragma unroll
            for (int r = 0; r < 4; r++) O[dt][r] = 0.f;
        float mrow[2];
        float lrow[2];
        mrow[0] = -1e30f; mrow[1] = -1e30f;
        lrow[0] = 0.f;    lrow[1] = 0.f;

#pragma unroll 1
        for (int kt = 0; kt <= qt; kt++) {
            cp_wait<0>();
            __syncthreads();
            if (kt < qt) LOAD_KV(kt + 1, (kt + 1) & 1);

            const __half* sK_ = sK0 + (kt & 1) * 64 * SK_STRIDE;
            const __half* sV_ = sV0 + (kt & 1) * 64 * SV_STRIDE;

            float S[8][4];
#pragma unroll
            for (int nt = 0; nt < 8; nt++)
#pragma unroll
                for (int r = 0; r < 4; r++) S[nt][r] = 0.f;

            const int klr = (lane >> 4) * 8 + (lane & 7);
            const int klc = ((lane >> 3) & 1) * 8;
#pragma unroll
            for (int ks = 0; ks < 4; ks++) {
#pragma unroll
                for (int jp = 0; jp < 4; jp++) {
                    uint32_t b0, b1, b2, b3;
                    ldm_x4(b0, b1, b2, b3,
                           smem_u32(sK_ + (jp * 16 + klr) * SK_STRIDE + ks * 16 + klc));
                    mma16816(S[jp * 2 + 0], qf[ks][0], qf[ks][1], qf[ks][2], qf[ks][3], b0, b1);
                    mma16816(S[jp * 2 + 1], qf[ks][0], qf[ks][1], qf[ks][2], qf[ks][3], b2, b3);
                }
            }

            if (kt == qt) {
#pragma unroll
                for (int nt = 0; nt < 8; nt++) {
                    const int jc = nt * 8 + 2 * (lane & 3);
#pragma unroll
                    for (int ri = 0; ri < 2; ri++) {
                        const int ii = qrow0 + ri * 8;
                        if (jc     > ii) S[nt][ri * 2 + 0] = -1e30f;
                        if (jc + 1 > ii) S[nt][ri * 2 + 1] = -1e30f;
                    }
                }
            }

            // online softmax in base-2 domain (q pre-scaled by log2e/8)
#pragma unroll
            for (int ri = 0; ri < 2; ri++) {
                float tmax = -1e30f;
#pragma unroll
                for (int nt = 0; nt < 8; nt++)
                    tmax = fmaxf(tmax, fmaxf(S[nt][ri * 2], S[nt][ri * 2 + 1]));
                tmax = fmaxf(tmax, __shfl_xor_sync(0xffffffffu, tmax, 1));
                tmax = fmaxf(tmax, __shfl_xor_sync(0xffffffffu, tmax, 2));
                const float mnew = fmaxf(mrow[ri], tmax);
                const float scale = exp2f(mrow[ri] - mnew);
                float rs = 0.f;
#pragma unroll
                for (int nt = 0; nt < 8; nt++) {
                    float p0 = exp2f(S[nt][ri * 2 + 0] - mnew);
                    float p1 = exp2f(S[nt][ri * 2 + 1] - mnew);
                    S[nt][ri * 2 + 0] = p0;
                    S[nt][ri * 2 + 1] = p1;
                    rs += p0 + p1;
                }
                rs += __shfl_xor_sync(0xffffffffu, rs, 1);
                rs += __shfl_xor_sync(0xffffffffu, rs, 2);
                lrow[ri] = lrow[ri] * scale + rs;
                mrow[ri] = mnew;
#pragma unroll
                for (int dt = 0; dt < 8; dt++) {
                    O[dt][ri * 2 + 0] *= scale;
                    O[dt][ri * 2 + 1] *= scale;
                }
            }

            const int vrow = lane & 15;
            const int vcol = (lane >> 4) * 8;
#pragma unroll
            for (int kk = 0; kk < 4; kk++) {
                uint32_t a0 = packh2(S[kk * 2 + 0][0], S[kk * 2 + 0][1]);
                uint32_t a1 = packh2(S[kk * 2 + 0][2], S[kk * 2 + 0][3]);
                uint32_t a2 = packh2(S[kk * 2 + 1][0], S[kk * 2 + 1][1]);
                uint32_t a3 = packh2(S[kk * 2 + 1][2], S[kk * 2 + 1][3]);
#pragma unroll
                for (int dp = 0; dp < 4; dp++) {
                    uint32_t b0, b1, b2, b3;
                    ldm_x4_t(b0, b1, b2, b3,
                             smem_u32(sV_ + (kk * 16 + vrow) * SV_STRIDE + dp * 16 + vcol));
                    mma16816(O[dp * 2 + 0], a0, a1, a2, a3, b0, b1);
                    mma16816(O[dp * 2 + 1], a0, a1, a2, a3, b2, b3);
                }
            }
        }

        // normalize + write ctx fp16 [B*S, EMB]
#pragma unroll
        for (int ri = 0; ri < 2; ri++) {
            const float inv = 1.f / lrow[ri];
            const size_t mg = mbase + (size_t)qt * 64 + qrow0 + ri * 8;
#pragma unroll
            for (int dt = 0; dt < 8; dt++) {
                const int col = hh * 64 + dt * 8 + 2 * (lane & 3);
                __half2 hv = __floats2half2_rn(O[dt][ri * 2 + 0] * inv, O[dt][ri * 2 + 1] * inv);
                *(__half2*)(g_ctx + mg * EMB + col) = hv;
            }
        }
    }
#undef LOAD_KV
}

// ---------------------------------------------------------------------------
extern "C" void kernel_launch(void* const* d_in, const int* in_sizes, int n_in,
                              void* d_out, int out_size)
{
    const float* x     = (const float*)d_in[0];
    const float* w_qkv = (const float*)d_in[1];
    const float* b_qkv = (const float*)d_in[2];
    const float* w_fc  = (const float*)d_in[3];
    const float* b_fc  = (const float*)d_in[4];
    float* out = (float*)d_out;

    static int attr_done = 0;
    if (!attr_done) {
        cudaFuncSetAttribute(hgemm_kernel<0>, cudaFuncAttributeMaxDynamicSharedMemorySize, HGEMM_SMEM);
        cudaFuncSetAttribute(hgemm_kernel<1>, cudaFuncAttributeMaxDynamicSharedMemorySize, HGEMM_SMEM);
        cudaFuncSetAttribute(flash_kernel, cudaFuncAttributeMaxDynamicSharedMemorySize, FLASH_SMEM);
        attr_done = 1;
    }

    // 0) one merged fp32->fp16 convert for x, w_qkv, w_fc
    convert_all_kernel<<<(int)((NX + NW0 + NW1) / 8 / 256), 256>>>(x, w_qkv, w_fc);

    // 1) QKV projection (4-stage pipeline)
    hgemm_kernel<0><<<dim3(24, 64), 128, HGEMM_SMEM>>>(b_qkv, nullptr, 3 * EMB);

    // 2) causal flash attention (R14 engine: paired q-tiles, exp2)
    flash_kernel<<<dim3(SEQ / 128, HEADS, BATCH), 128, FLASH_SMEM>>>();

    // 3) output projection (4-stage pipeline)
    hgemm_kernel<1><<<dim3(8, 64), 128, HGEMM_SMEM>>>(b_fc, out, EMB);
}